// round 6
// baseline (speedup 1.0000x reference)
#include <cuda_runtime.h>
#include <math_constants.h>

#define N_NODES 50000
#define N_EDGES 800000
#define DIM 64
#define NCHUNK 98          // 98*512 = 50176 >= 50000 ; co-resident for lookback scan
#define NQ (N_EDGES / 4)
#define NHALF (NQ / 2)

// ---- device scratch (no allocations allowed; static zero-init) ----
__device__ int   g_counts[N_NODES];      // invariant: zero at entry of every replay
__device__ int   g_offsets[N_NODES + 1];
__device__ int   g_cursor[N_NODES];
__device__ int   g_csum[NCHUNK];
__device__ volatile int g_cflag[NCHUNK]; // invariant: zero at entry (reset by k_scatter)
__device__ int   g_srcidx[N_EDGES];
__device__ float g_h0[N_NODES * DIM];
__device__ float g_h1[N_NODES * DIM];

// ---------------- CSR build ----------------

__global__ void k_count(const int* __restrict__ dst) {
    int i = blockIdx.x * blockDim.x + threadIdx.x;
    if (i < NHALF) {
        int4 a = __ldg((const int4*)dst + i);
        int4 b = __ldg((const int4*)dst + i + NHALF);
        atomicAdd(&g_counts[a.x], 1);
        atomicAdd(&g_counts[a.y], 1);
        atomicAdd(&g_counts[a.z], 1);
        atomicAdd(&g_counts[a.w], 1);
        atomicAdd(&g_counts[b.x], 1);
        atomicAdd(&g_counts[b.y], 1);
        atomicAdd(&g_counts[b.z], 1);
        atomicAdd(&g_counts[b.w], 1);
    }
}

// single-kernel scan via decoupled lookback (all 98 blocks co-resident)
__global__ void __launch_bounds__(512) k_scan() {
    __shared__ int warp_sums[16];
    __shared__ int prefix_s;
    const int t = threadIdx.x, lane = t & 31, wid = t >> 5;
    const int c = blockIdx.x;
    const int i = c * 512 + t;

    int v = (i < N_NODES) ? g_counts[i] : 0;
    int s = v;
    #pragma unroll
    for (int d = 1; d < 32; d <<= 1) {
        int y = __shfl_up_sync(0xffffffffu, s, d);
        if (lane >= d) s += y;
    }
    if (lane == 31) warp_sums[wid] = s;
    __syncthreads();
    if (wid == 0 && lane < 16) {
        int ws = warp_sums[lane];
        #pragma unroll
        for (int d = 1; d < 16; d <<= 1) {
            int y = __shfl_up_sync(0xffffu, ws, d);
            if (lane >= d) ws += y;
        }
        warp_sums[lane] = ws;
    }
    __syncthreads();
    int excl = s - v + (wid > 0 ? warp_sums[wid - 1] : 0);

    if (t == 511) {
        g_csum[c] = excl + v;
        __threadfence();
        g_cflag[c] = 1;
    }
    if (t < 32) {
        int acc = 0;
        for (int j = lane; j < c; j += 32) {
            while (g_cflag[j] == 0) { }
            acc += *(volatile int*)&g_csum[j];
        }
        #pragma unroll
        for (int d = 16; d > 0; d >>= 1) acc += __shfl_down_sync(0xffffffffu, acc, d);
        if (lane == 0) prefix_s = acc;
    }
    __syncthreads();
    int prefix = prefix_s;

    if (i < N_NODES) {
        int o = excl + prefix;
        g_offsets[i] = o;
        g_cursor[i]  = o;
        g_counts[i]  = 0;
    }
    if (c == NCHUNK - 1 && t == 511)
        g_offsets[N_NODES] = prefix + excl + v;
}

__global__ void k_scatter(const int* __restrict__ src, const int* __restrict__ dst) {
    int i = blockIdx.x * blockDim.x + threadIdx.x;
    if (i < NCHUNK) g_cflag[i] = 0;
    if (i < NHALF) {
        int4 sa = __ldg((const int4*)src + i);
        int4 da = __ldg((const int4*)dst + i);
        int4 sb = __ldg((const int4*)src + i + NHALF);
        int4 db = __ldg((const int4*)dst + i + NHALF);
        g_srcidx[atomicAdd(&g_cursor[da.x], 1)] = sa.x;
        g_srcidx[atomicAdd(&g_cursor[da.y], 1)] = sa.y;
        g_srcidx[atomicAdd(&g_cursor[da.z], 1)] = sa.z;
        g_srcidx[atomicAdd(&g_cursor[da.w], 1)] = sa.w;
        g_srcidx[atomicAdd(&g_cursor[db.x], 1)] = sb.x;
        g_srcidx[atomicAdd(&g_cursor[db.y], 1)] = sb.y;
        g_srcidx[atomicAdd(&g_cursor[db.z], 1)] = sb.z;
        g_srcidx[atomicAdd(&g_cursor[db.w], 1)] = sb.w;
    }
}

// ---------------- fused layer: agg (segment-max) + GEMM + bias + leaky-relu ----
// 256 threads, tile = 64 nodes. Agg: 8 warps x 8 nodes. GEMM: 4 nodes x 4 cols
// per thread, k-chunked float4 X loads (broadcast, no smem padding needed).
__global__ void __launch_bounds__(256, 5) k_layer(
        const float* __restrict__ h,
        const float* __restrict__ W,
        const float* __restrict__ bias,
        const float* __restrict__ eps, int layer,
        float* __restrict__ out, int activate) {
    __shared__ float Ws[64 * 64];     // [k][j]
    __shared__ float Xs[64 * 64];     // [node][k], stride 64 (reads are broadcasts)

    int t = threadIdx.x;              // 0..255
    int base = blockIdx.x * 64;

    // load W via float4 (1024 float4 over 256 threads)
    const float4* W4 = (const float4*)W;
    float4* Ws4 = (float4*)Ws;
    #pragma unroll
    for (int p = 0; p < 4; p++) Ws4[t + p * 256] = W4[t + p * 256];

    float ep = 1.0f + __ldg(eps + layer);
    int warp = t >> 5, lane = t & 31;

    // ---- phase 1: aggregation, warp handles 8 nodes, unroll 8 ----
    #pragma unroll
    for (int q = 0; q < 8; q++) {
        int nl = warp * 8 + q;
        int n = base + nl;
        if (n < N_NODES) {
            int beg = g_offsets[n];
            int end = g_offsets[n + 1];
            float m0 = -CUDART_INF_F, m1 = -CUDART_INF_F;
            int i = beg;
            for (; i + 8 <= end; i += 8) {
                int sx[8];
                #pragma unroll
                for (int u = 0; u < 8; u++) sx[u] = __ldg(&g_srcidx[i + u]);
                float2 a[8];
                #pragma unroll
                for (int u = 0; u < 8; u++)
                    a[u] = __ldg((const float2*)(h + (size_t)sx[u] * DIM) + lane);
                #pragma unroll
                for (int u = 0; u < 8; u++) {
                    m0 = fmaxf(m0, a[u].x);
                    m1 = fmaxf(m1, a[u].y);
                }
            }
            for (; i < end; ++i) {
                int s = __ldg(&g_srcidx[i]);
                float2 a = __ldg((const float2*)(h + (size_t)s * DIM) + lane);
                m0 = fmaxf(m0, a.x);
                m1 = fmaxf(m1, a.y);
            }
            if (beg == end) { m0 = 0.0f; m1 = 0.0f; }   // DGL zero-fill
            float2 hs = __ldg((const float2*)(h + (size_t)n * DIM) + lane);
            float2 xv;
            xv.x = fmaf(ep, hs.x, m0);
            xv.y = fmaf(ep, hs.y, m1);
            *(float2*)&Xs[nl * 64 + lane * 2] = xv;
        }
    }
    __syncthreads();

    // ---- phase 2: GEMM out[64x64] = Xs @ Ws + b, 4 nodes x 4 cols/thread ----
    int jg = t & 15;                  // column group (cols jg*4..+3)
    int ng = t >> 4;                  // node group (nodes ng*4..+3), 0..15

    float acc[4][4];
    float4 bj = *(const float4*)(bias + jg * 4);
    #pragma unroll
    for (int i = 0; i < 4; i++) {
        acc[i][0] = bj.x; acc[i][1] = bj.y; acc[i][2] = bj.z; acc[i][3] = bj.w;
    }

    #pragma unroll
    for (int kc = 0; kc < 64; kc += 4) {
        float xr[4][4];
        #pragma unroll
        for (int i = 0; i < 4; i++)
            *(float4*)xr[i] = *(const float4*)&Xs[(ng * 4 + i) * 64 + kc];
        #pragma unroll
        for (int u = 0; u < 4; u++) {
            float4 w = Ws4[(kc + u) * 16 + jg];
            #pragma unroll
            for (int i = 0; i < 4; i++) {
                float xk = xr[i][u];
                acc[i][0] = fmaf(xk, w.x, acc[i][0]);
                acc[i][1] = fmaf(xk, w.y, acc[i][1]);
                acc[i][2] = fmaf(xk, w.z, acc[i][2]);
                acc[i][3] = fmaf(xk, w.w, acc[i][3]);
            }
        }
    }

    #pragma unroll
    for (int i = 0; i < 4; i++) {
        int n = base + ng * 4 + i;
        if (n < N_NODES) {
            float4 v;
            v.x = acc[i][0]; v.y = acc[i][1]; v.z = acc[i][2]; v.w = acc[i][3];
            if (activate) {
                v.x = v.x >= 0.f ? v.x : 0.01f * v.x;
                v.y = v.y >= 0.f ? v.y : 0.01f * v.y;
                v.z = v.z >= 0.f ? v.z : 0.01f * v.z;
                v.w = v.w >= 0.f ? v.w : 0.01f * v.w;
            }
            *(float4*)&out[(size_t)n * DIM + jg * 4] = v;
        }
    }
}

// ---------------- launch ----------------
extern "C" void kernel_launch(void* const* d_in, const int* in_sizes, int n_in,
                              void* d_out, int out_size) {
    const float* n_feat = (const float*)d_in[0];
    const float* W0 = (const float*)d_in[1];
    const float* b0 = (const float*)d_in[2];
    const float* W1 = (const float*)d_in[3];
    const float* b1 = (const float*)d_in[4];
    const float* W2 = (const float*)d_in[5];
    const float* b2 = (const float*)d_in[6];
    const float* eps = (const float*)d_in[7];
    const int*   src = (const int*)d_in[8];
    const int*   dst = (const int*)d_in[9];
    float* out = (float*)d_out;

    float *h0_ptr, *h1_ptr;
    cudaGetSymbolAddress((void**)&h0_ptr, g_h0);
    cudaGetSymbolAddress((void**)&h1_ptr, g_h1);

    // CSR build (3 launches)
    k_count<<<(NHALF + 255) / 256, 256>>>(dst);
    k_scan<<<NCHUNK, 512>>>();
    k_scatter<<<(NHALF + 255) / 256, 256>>>(src, dst);

    const int layer_blocks = (N_NODES + 63) / 64;   // 782

    k_layer<<<layer_blocks, 256>>>(n_feat, W0, b0, eps, 0, h0_ptr, 1);
    k_layer<<<layer_blocks, 256>>>(h0_ptr, W1, b1, eps, 1, h1_ptr, 1);
    k_layer<<<layer_blocks, 256>>>(h1_ptr, W2, b2, eps, 2, out, 0);
}

// round 7
// speedup vs baseline: 1.0856x; 1.0856x over previous
#include <cuda_runtime.h>
#include <math_constants.h>

#define N_NODES 50000
#define N_EDGES 800000
#define DIM 64
#define NCHUNK 98          // 98*512 = 50176 >= 50000 ; co-resident for lookback scan
#define NQ (N_EDGES / 4)
#define NHALF (NQ / 2)

// ---- device scratch (no allocations allowed; static zero-init) ----
__device__ int   g_counts[N_NODES];      // invariant: zero at entry of every replay
__device__ int   g_offsets[N_NODES + 1];
__device__ int   g_cursor[N_NODES];
__device__ int   g_csum[NCHUNK];
__device__ volatile int g_cflag[NCHUNK]; // invariant: zero at entry (reset by k_scatter)
__device__ int   g_srcidx[N_EDGES];
__device__ float g_h0[N_NODES * DIM];
__device__ float g_h1[N_NODES * DIM];

// ---------------- CSR build ----------------

__global__ void k_count(const int* __restrict__ dst) {
    int i = blockIdx.x * blockDim.x + threadIdx.x;
    if (i < NHALF) {
        int4 a = __ldg((const int4*)dst + i);
        int4 b = __ldg((const int4*)dst + i + NHALF);
        atomicAdd(&g_counts[a.x], 1);
        atomicAdd(&g_counts[a.y], 1);
        atomicAdd(&g_counts[a.z], 1);
        atomicAdd(&g_counts[a.w], 1);
        atomicAdd(&g_counts[b.x], 1);
        atomicAdd(&g_counts[b.y], 1);
        atomicAdd(&g_counts[b.z], 1);
        atomicAdd(&g_counts[b.w], 1);
    }
}

// single-kernel scan via decoupled lookback (all 98 blocks co-resident)
__global__ void __launch_bounds__(512) k_scan() {
    __shared__ int warp_sums[16];
    __shared__ int prefix_s;
    const int t = threadIdx.x, lane = t & 31, wid = t >> 5;
    const int c = blockIdx.x;
    const int i = c * 512 + t;

    int v = (i < N_NODES) ? g_counts[i] : 0;
    int s = v;
    #pragma unroll
    for (int d = 1; d < 32; d <<= 1) {
        int y = __shfl_up_sync(0xffffffffu, s, d);
        if (lane >= d) s += y;
    }
    if (lane == 31) warp_sums[wid] = s;
    __syncthreads();
    if (wid == 0 && lane < 16) {
        int ws = warp_sums[lane];
        #pragma unroll
        for (int d = 1; d < 16; d <<= 1) {
            int y = __shfl_up_sync(0xffffu, ws, d);
            if (lane >= d) ws += y;
        }
        warp_sums[lane] = ws;
    }
    __syncthreads();
    int excl = s - v + (wid > 0 ? warp_sums[wid - 1] : 0);

    if (t == 511) {
        g_csum[c] = excl + v;
        __threadfence();
        g_cflag[c] = 1;
    }
    if (t < 32) {
        int acc = 0;
        for (int j = lane; j < c; j += 32) {
            while (g_cflag[j] == 0) { }
            acc += *(volatile int*)&g_csum[j];
        }
        #pragma unroll
        for (int d = 16; d > 0; d >>= 1) acc += __shfl_down_sync(0xffffffffu, acc, d);
        if (lane == 0) prefix_s = acc;
    }
    __syncthreads();
    int prefix = prefix_s;

    if (i < N_NODES) {
        int o = excl + prefix;
        g_offsets[i] = o;
        g_cursor[i]  = o;
        g_counts[i]  = 0;
    }
    if (c == NCHUNK - 1 && t == 511)
        g_offsets[N_NODES] = prefix + excl + v;
}

__global__ void k_scatter(const int* __restrict__ src, const int* __restrict__ dst) {
    int i = blockIdx.x * blockDim.x + threadIdx.x;
    if (i < NCHUNK) g_cflag[i] = 0;
    if (i < NHALF) {
        int4 sa = __ldg((const int4*)src + i);
        int4 da = __ldg((const int4*)dst + i);
        int4 sb = __ldg((const int4*)src + i + NHALF);
        int4 db = __ldg((const int4*)dst + i + NHALF);
        g_srcidx[atomicAdd(&g_cursor[da.x], 1)] = sa.x;
        g_srcidx[atomicAdd(&g_cursor[da.y], 1)] = sa.y;
        g_srcidx[atomicAdd(&g_cursor[da.z], 1)] = sa.z;
        g_srcidx[atomicAdd(&g_cursor[da.w], 1)] = sa.w;
        g_srcidx[atomicAdd(&g_cursor[db.x], 1)] = sb.x;
        g_srcidx[atomicAdd(&g_cursor[db.y], 1)] = sb.y;
        g_srcidx[atomicAdd(&g_cursor[db.z], 1)] = sb.z;
        g_srcidx[atomicAdd(&g_cursor[db.w], 1)] = sb.w;
    }
}

// ---------------- fused layer: agg (segment-max) + GEMM + bias + leaky-relu ----
// 512 threads, tile = 64 nodes.
// Agg: HALF-WARP per node (float4 gathers, 16 lanes x 16B = 256B/edge);
//      each warp processes 2 nodes concurrently, 2 outer iterations.
// GEMM: 2 nodes x 4 cols per thread (R5 structure, 32 regs).
__global__ void __launch_bounds__(512, 3) k_layer(
        const float* __restrict__ h,
        const float* __restrict__ W,
        const float* __restrict__ bias,
        const float* __restrict__ eps, int layer,
        float* __restrict__ out, int activate) {
    __shared__ float Ws[64 * 64];     // [k][j]
    __shared__ float Xs[64 * 68];     // padded stride 68 (272B rows, 16B aligned)

    int t = threadIdx.x;              // 0..511
    int base = blockIdx.x * 64;

    // load W via float4 (1024 float4 over 512 threads)
    const float4* W4 = (const float4*)W;
    float4* Ws4 = (float4*)Ws;
    Ws4[t]       = W4[t];
    Ws4[t + 512] = W4[t + 512];

    float ep = 1.0f + __ldg(eps + layer);
    int warp = t >> 5, lane = t & 31;
    int half = lane >> 4;             // 0 or 1
    int hl   = lane & 15;             // lane within half-warp

    // ---- phase 1: aggregation, half-warp per node, 4 edges in flight/half ----
    #pragma unroll
    for (int q = 0; q < 2; q++) {
        int nl = warp * 4 + q * 2 + half;    // local node 0..63
        int n = base + nl;
        if (n < N_NODES) {
            int beg = g_offsets[n];
            int end = g_offsets[n + 1];
            float4 m = make_float4(-CUDART_INF_F, -CUDART_INF_F,
                                   -CUDART_INF_F, -CUDART_INF_F);
            int i = beg;
            for (; i + 4 <= end; i += 4) {
                int s0 = __ldg(&g_srcidx[i + 0]);
                int s1 = __ldg(&g_srcidx[i + 1]);
                int s2 = __ldg(&g_srcidx[i + 2]);
                int s3 = __ldg(&g_srcidx[i + 3]);
                float4 a0 = __ldg((const float4*)(h + (size_t)s0 * DIM) + hl);
                float4 a1 = __ldg((const float4*)(h + (size_t)s1 * DIM) + hl);
                float4 a2 = __ldg((const float4*)(h + (size_t)s2 * DIM) + hl);
                float4 a3 = __ldg((const float4*)(h + (size_t)s3 * DIM) + hl);
                m.x = fmaxf(m.x, fmaxf(fmaxf(a0.x, a1.x), fmaxf(a2.x, a3.x)));
                m.y = fmaxf(m.y, fmaxf(fmaxf(a0.y, a1.y), fmaxf(a2.y, a3.y)));
                m.z = fmaxf(m.z, fmaxf(fmaxf(a0.z, a1.z), fmaxf(a2.z, a3.z)));
                m.w = fmaxf(m.w, fmaxf(fmaxf(a0.w, a1.w), fmaxf(a2.w, a3.w)));
            }
            for (; i < end; ++i) {
                int s = __ldg(&g_srcidx[i]);
                float4 a = __ldg((const float4*)(h + (size_t)s * DIM) + hl);
                m.x = fmaxf(m.x, a.x);
                m.y = fmaxf(m.y, a.y);
                m.z = fmaxf(m.z, a.z);
                m.w = fmaxf(m.w, a.w);
            }
            if (beg == end) { m.x = 0.f; m.y = 0.f; m.z = 0.f; m.w = 0.f; }
            float4 hs = __ldg((const float4*)(h + (size_t)n * DIM) + hl);
            float4 xv;
            xv.x = fmaf(ep, hs.x, m.x);
            xv.y = fmaf(ep, hs.y, m.y);
            xv.z = fmaf(ep, hs.z, m.z);
            xv.w = fmaf(ep, hs.w, m.w);
            *(float4*)&Xs[nl * 68 + hl * 4] = xv;
        }
    }
    __syncthreads();

    // ---- phase 2: GEMM out[64x64] = Xs @ Ws + b (2 nodes x 4 cols/thread) ----
    int jg = t & 15;                  // column group (4 cols)
    int ng = t >> 4;                  // node group (2 nodes), 0..31

    float acc[2][4];
    float4 bj = *(const float4*)(bias + jg * 4);
    #pragma unroll
    for (int i = 0; i < 2; i++) {
        acc[i][0] = bj.x; acc[i][1] = bj.y; acc[i][2] = bj.z; acc[i][3] = bj.w;
    }

    #pragma unroll
    for (int k = 0; k < 64; k++) {
        float4 w = *(const float4*)&Ws[k * 64 + jg * 4];
        float x0 = Xs[(ng * 2 + 0) * 68 + k];
        float x1 = Xs[(ng * 2 + 1) * 68 + k];
        acc[0][0] = fmaf(x0, w.x, acc[0][0]);
        acc[0][1] = fmaf(x0, w.y, acc[0][1]);
        acc[0][2] = fmaf(x0, w.z, acc[0][2]);
        acc[0][3] = fmaf(x0, w.w, acc[0][3]);
        acc[1][0] = fmaf(x1, w.x, acc[1][0]);
        acc[1][1] = fmaf(x1, w.y, acc[1][1]);
        acc[1][2] = fmaf(x1, w.z, acc[1][2]);
        acc[1][3] = fmaf(x1, w.w, acc[1][3]);
    }

    #pragma unroll
    for (int i = 0; i < 2; i++) {
        int n = base + ng * 2 + i;
        if (n < N_NODES) {
            float4 v;
            v.x = acc[i][0]; v.y = acc[i][1]; v.z = acc[i][2]; v.w = acc[i][3];
            if (activate) {
                v.x = v.x >= 0.f ? v.x : 0.01f * v.x;
                v.y = v.y >= 0.f ? v.y : 0.01f * v.y;
                v.z = v.z >= 0.f ? v.z : 0.01f * v.z;
                v.w = v.w >= 0.f ? v.w : 0.01f * v.w;
            }
            *(float4*)&out[(size_t)n * DIM + jg * 4] = v;
        }
    }
}

// ---------------- launch ----------------
extern "C" void kernel_launch(void* const* d_in, const int* in_sizes, int n_in,
                              void* d_out, int out_size) {
    const float* n_feat = (const float*)d_in[0];
    const float* W0 = (const float*)d_in[1];
    const float* b0 = (const float*)d_in[2];
    const float* W1 = (const float*)d_in[3];
    const float* b1 = (const float*)d_in[4];
    const float* W2 = (const float*)d_in[5];
    const float* b2 = (const float*)d_in[6];
    const float* eps = (const float*)d_in[7];
    const int*   src = (const int*)d_in[8];
    const int*   dst = (const int*)d_in[9];
    float* out = (float*)d_out;

    float *h0_ptr, *h1_ptr;
    cudaGetSymbolAddress((void**)&h0_ptr, g_h0);
    cudaGetSymbolAddress((void**)&h1_ptr, g_h1);

    // CSR build (3 launches)
    k_count<<<(NHALF + 255) / 256, 256>>>(dst);
    k_scan<<<NCHUNK, 512>>>();
    k_scatter<<<(NHALF + 255) / 256, 256>>>(src, dst);

    const int layer_blocks = (N_NODES + 63) / 64;   // 782

    k_layer<<<layer_blocks, 512>>>(n_feat, W0, b0, eps, 0, h0_ptr, 1);
    k_layer<<<layer_blocks, 512>>>(h0_ptr, W1, b1, eps, 1, h1_ptr, 1);
    k_layer<<<layer_blocks, 512>>>(h1_ptr, W2, b2, eps, 2, out, 0);
}

// round 8
// speedup vs baseline: 1.1031x; 1.0161x over previous
#include <cuda_runtime.h>
#include <math_constants.h>

#define N_NODES 50000
#define N_EDGES 800000
#define DIM 64
#define NCHUNK 98          // 98*512 = 50176 >= 50000 ; co-resident for lookback scan
#define NQ (N_EDGES / 4)
#define NHALF (NQ / 2)

// ---- device scratch (no allocations allowed; static zero-init) ----
__device__ int   g_counts[N_NODES];      // invariant: zero at entry of every replay
__device__ int   g_offsets[N_NODES + 1];
__device__ int   g_cursor[N_NODES];
__device__ int   g_csum[NCHUNK];
__device__ volatile int g_cflag[NCHUNK]; // invariant: zero at entry (reset by k_scatter)
__device__ int   g_srcidx[N_EDGES];
__device__ float g_h0[N_NODES * DIM];
__device__ float g_h1[N_NODES * DIM];

// ---- packed f32x2 helpers (Blackwell FFMA2 path, PTX-only) ----
__device__ __forceinline__ unsigned long long pk2(float lo, float hi) {
    unsigned long long r;
    asm("mov.b64 %0, {%1, %2};" : "=l"(r) : "f"(lo), "f"(hi));
    return r;
}
__device__ __forceinline__ void fma2(unsigned long long& d,
                                     unsigned long long a,
                                     unsigned long long b) {
    asm("fma.rn.f32x2 %0, %1, %2, %0;" : "+l"(d) : "l"(a), "l"(b));
}
__device__ __forceinline__ void upk2(float& lo, float& hi, unsigned long long v) {
    asm("mov.b64 {%0, %1}, %2;" : "=f"(lo), "=f"(hi) : "l"(v));
}

// ---------------- CSR build ----------------

__global__ void k_count(const int* __restrict__ dst) {
    int i = blockIdx.x * blockDim.x + threadIdx.x;
    if (i < NHALF) {
        int4 a = __ldg((const int4*)dst + i);
        int4 b = __ldg((const int4*)dst + i + NHALF);
        atomicAdd(&g_counts[a.x], 1);
        atomicAdd(&g_counts[a.y], 1);
        atomicAdd(&g_counts[a.z], 1);
        atomicAdd(&g_counts[a.w], 1);
        atomicAdd(&g_counts[b.x], 1);
        atomicAdd(&g_counts[b.y], 1);
        atomicAdd(&g_counts[b.z], 1);
        atomicAdd(&g_counts[b.w], 1);
    }
}

// single-kernel scan via decoupled lookback (all 98 blocks co-resident)
__global__ void __launch_bounds__(512) k_scan() {
    __shared__ int warp_sums[16];
    __shared__ int prefix_s;
    const int t = threadIdx.x, lane = t & 31, wid = t >> 5;
    const int c = blockIdx.x;
    const int i = c * 512 + t;

    int v = (i < N_NODES) ? g_counts[i] : 0;
    int s = v;
    #pragma unroll
    for (int d = 1; d < 32; d <<= 1) {
        int y = __shfl_up_sync(0xffffffffu, s, d);
        if (lane >= d) s += y;
    }
    if (lane == 31) warp_sums[wid] = s;
    __syncthreads();
    if (wid == 0 && lane < 16) {
        int ws = warp_sums[lane];
        #pragma unroll
        for (int d = 1; d < 16; d <<= 1) {
            int y = __shfl_up_sync(0xffffu, ws, d);
            if (lane >= d) ws += y;
        }
        warp_sums[lane] = ws;
    }
    __syncthreads();
    int excl = s - v + (wid > 0 ? warp_sums[wid - 1] : 0);

    if (t == 511) {
        g_csum[c] = excl + v;
        __threadfence();
        g_cflag[c] = 1;
    }
    if (t < 32) {
        int acc = 0;
        for (int j = lane; j < c; j += 32) {
            while (g_cflag[j] == 0) { }
            acc += *(volatile int*)&g_csum[j];
        }
        #pragma unroll
        for (int d = 16; d > 0; d >>= 1) acc += __shfl_down_sync(0xffffffffu, acc, d);
        if (lane == 0) prefix_s = acc;
    }
    __syncthreads();
    int prefix = prefix_s;

    if (i < N_NODES) {
        int o = excl + prefix;
        g_offsets[i] = o;
        g_cursor[i]  = o;
        g_counts[i]  = 0;
    }
    if (c == NCHUNK - 1 && t == 511)
        g_offsets[N_NODES] = prefix + excl + v;
}

__global__ void k_scatter(const int* __restrict__ src, const int* __restrict__ dst) {
    int i = blockIdx.x * blockDim.x + threadIdx.x;
    if (i < NCHUNK) g_cflag[i] = 0;
    if (i < NHALF) {
        int4 sa = __ldg((const int4*)src + i);
        int4 da = __ldg((const int4*)dst + i);
        int4 sb = __ldg((const int4*)src + i + NHALF);
        int4 db = __ldg((const int4*)dst + i + NHALF);
        g_srcidx[atomicAdd(&g_cursor[da.x], 1)] = sa.x;
        g_srcidx[atomicAdd(&g_cursor[da.y], 1)] = sa.y;
        g_srcidx[atomicAdd(&g_cursor[da.z], 1)] = sa.z;
        g_srcidx[atomicAdd(&g_cursor[da.w], 1)] = sa.w;
        g_srcidx[atomicAdd(&g_cursor[db.x], 1)] = sb.x;
        g_srcidx[atomicAdd(&g_cursor[db.y], 1)] = sb.y;
        g_srcidx[atomicAdd(&g_cursor[db.z], 1)] = sb.z;
        g_srcidx[atomicAdd(&g_cursor[db.w], 1)] = sb.w;
    }
}

// ---------------- fused layer: agg (segment-max) + GEMM + bias + leaky-relu ----
// 512 threads, tile = 64 nodes.
// Agg: warp per node (4 nodes/warp), float2 gathers, batch-8 with INDEX PREFETCH
//      (next batch's indices load while current batch's gathers are in flight).
// GEMM: 2 nodes x 4 cols per thread using packed fma.rn.f32x2 (FFMA2).
__global__ void __launch_bounds__(512, 3) k_layer(
        const float* __restrict__ h,
        const float* __restrict__ W,
        const float* __restrict__ bias,
        const float* __restrict__ eps, int layer,
        float* __restrict__ out, int activate) {
    __shared__ float Ws[64 * 64];     // [k][j]
    __shared__ float Xs[64 * 68];     // padded stride 68

    int t = threadIdx.x;              // 0..511
    int base = blockIdx.x * 64;

    // load W via float4 (1024 float4 over 512 threads)
    const float4* W4 = (const float4*)W;
    float4* Ws4 = (float4*)Ws;
    Ws4[t]       = W4[t];
    Ws4[t + 512] = W4[t + 512];

    float ep = 1.0f + __ldg(eps + layer);
    int warp = t >> 5, lane = t & 31;

    // ---- phase 1: aggregation with pipelined index prefetch ----
    #pragma unroll
    for (int q = 0; q < 4; q++) {
        int nl = warp * 4 + q;
        int n = base + nl;
        if (n < N_NODES) {
            int beg = g_offsets[n];
            int end = g_offsets[n + 1];
            float m0 = -CUDART_INF_F, m1 = -CUDART_INF_F;
            int i = beg;
            int cur[8];
            bool have = (i + 8 <= end);
            if (have) {
                #pragma unroll
                for (int u = 0; u < 8; u++) cur[u] = __ldg(&g_srcidx[i + u]);
            }
            while (have) {
                int ni = i + 8;
                bool nhave = (ni + 8 <= end);
                int nxt[8];
                if (nhave) {
                    #pragma unroll
                    for (int u = 0; u < 8; u++) nxt[u] = __ldg(&g_srcidx[ni + u]);
                }
                float2 a[8];
                #pragma unroll
                for (int u = 0; u < 8; u++)
                    a[u] = __ldg((const float2*)(h + (size_t)cur[u] * DIM) + lane);
                #pragma unroll
                for (int u = 0; u < 8; u++) {
                    m0 = fmaxf(m0, a[u].x);
                    m1 = fmaxf(m1, a[u].y);
                }
                i = ni;
                #pragma unroll
                for (int u = 0; u < 8; u++) cur[u] = nxt[u];
                have = nhave;
            }
            for (; i < end; ++i) {
                int s = __ldg(&g_srcidx[i]);
                float2 a = __ldg((const float2*)(h + (size_t)s * DIM) + lane);
                m0 = fmaxf(m0, a.x);
                m1 = fmaxf(m1, a.y);
            }
            if (beg == end) { m0 = 0.0f; m1 = 0.0f; }   // DGL zero-fill
            float2 hs = __ldg((const float2*)(h + (size_t)n * DIM) + lane);
            float2 xv;
            xv.x = fmaf(ep, hs.x, m0);
            xv.y = fmaf(ep, hs.y, m1);
            *(float2*)&Xs[nl * 68 + lane * 2] = xv;
        }
    }
    __syncthreads();

    // ---- phase 2: GEMM out[64x64] = Xs @ Ws + b, packed f32x2 FMA ----
    int jg = t & 15;                  // column group (4 cols)
    int ng = t >> 4;                  // node group (2 nodes), 0..31

    float4 bj = *(const float4*)(bias + jg * 4);
    unsigned long long a00 = pk2(bj.x, bj.y);   // node0 cols 0-1
    unsigned long long a01 = pk2(bj.z, bj.w);   // node0 cols 2-3
    unsigned long long a10 = a00;               // node1 cols 0-1
    unsigned long long a11 = a01;               // node1 cols 2-3

    const unsigned long long* Wp = (const unsigned long long*)Ws;  // pairs
    int wrow = jg * 2;                // pair index of col jg*4 within a 32-pair row

    #pragma unroll
    for (int k = 0; k < 64; k++) {
        unsigned long long w01 = Wp[k * 32 + wrow];      // (W[k][4jg],   W[k][4jg+1])
        unsigned long long w23 = Wp[k * 32 + wrow + 1];  // (W[k][4jg+2], W[k][4jg+3])
        float x0 = Xs[(ng * 2 + 0) * 68 + k];
        float x1 = Xs[(ng * 2 + 1) * 68 + k];
        unsigned long long x00 = pk2(x0, x0);
        unsigned long long x11 = pk2(x1, x1);
        fma2(a00, x00, w01);
        fma2(a01, x00, w23);
        fma2(a10, x11, w01);
        fma2(a11, x11, w23);
    }

    float r[2][4];
    upk2(r[0][0], r[0][1], a00);
    upk2(r[0][2], r[0][3], a01);
    upk2(r[1][0], r[1][1], a10);
    upk2(r[1][2], r[1][3], a11);

    #pragma unroll
    for (int i = 0; i < 2; i++) {
        int n = base + ng * 2 + i;
        if (n < N_NODES) {
            float4 v;
            v.x = r[i][0]; v.y = r[i][1]; v.z = r[i][2]; v.w = r[i][3];
            if (activate) {
                v.x = v.x >= 0.f ? v.x : 0.01f * v.x;
                v.y = v.y >= 0.f ? v.y : 0.01f * v.y;
                v.z = v.z >= 0.f ? v.z : 0.01f * v.z;
                v.w = v.w >= 0.f ? v.w : 0.01f * v.w;
            }
            *(float4*)&out[(size_t)n * DIM + jg * 4] = v;
        }
    }
}

// ---------------- launch ----------------
extern "C" void kernel_launch(void* const* d_in, const int* in_sizes, int n_in,
                              void* d_out, int out_size) {
    const float* n_feat = (const float*)d_in[0];
    const float* W0 = (const float*)d_in[1];
    const float* b0 = (const float*)d_in[2];
    const float* W1 = (const float*)d_in[3];
    const float* b1 = (const float*)d_in[4];
    const float* W2 = (const float*)d_in[5];
    const float* b2 = (const float*)d_in[6];
    const float* eps = (const float*)d_in[7];
    const int*   src = (const int*)d_in[8];
    const int*   dst = (const int*)d_in[9];
    float* out = (float*)d_out;

    float *h0_ptr, *h1_ptr;
    cudaGetSymbolAddress((void**)&h0_ptr, g_h0);
    cudaGetSymbolAddress((void**)&h1_ptr, g_h1);

    // CSR build (3 launches)
    k_count<<<(NHALF + 255) / 256, 256>>>(dst);
    k_scan<<<NCHUNK, 512>>>();
    k_scatter<<<(NHALF + 255) / 256, 256>>>(src, dst);

    const int layer_blocks = (N_NODES + 63) / 64;   // 782

    k_layer<<<layer_blocks, 512>>>(n_feat, W0, b0, eps, 0, h0_ptr, 1);
    k_layer<<<layer_blocks, 512>>>(h0_ptr, W1, b1, eps, 1, h1_ptr, 1);
    k_layer<<<layer_blocks, 512>>>(h1_ptr, W2, b2, eps, 2, out, 0);
}